// round 13
// baseline (speedup 1.0000x reference)
#include <cuda_runtime.h>
#include <cuda_fp16.h>
#include <cstdint>
#include <cstddef>

#define DEVI __device__ __forceinline__

static constexpr int B_   = 16384;
static constexpr int H_   = 512;
static constexpr int KP   = 1312;   // padded K: 41 tiles of 32
static constexpr int NKT  = 41;
static constexpr int NTOT = 3072;   // 6 gate blocks * 512

// GEMM tiling
static constexpr int BM = 256, BN = 128, BK = 32;
static constexpr int NST = 4;                        // cp.async stages
static constexpr int APADF = 40;                     // A row stride in floats (160 B)
static constexpr int ASTG = BM * APADF * 4;          // 40960 B (fp32 A tile)
static constexpr int BSTG = BN * BK * 2;             // 8192 B (fp16 fragment-packed)
static constexpr int STG  = ASTG + BSTG;             // 49152 B
static constexpr int SMEM_GEMM = NST * STG;          // 196608 B

// n-block order (heavy-first): 0=i 1=f 2=o 3=cand 4=tx 5=tt
__device__ __half g_Gp[(size_t)(NTOT / 128) * NKT * 4096];  // permuted fp16 weights
__device__ __half g_zh[(size_t)B_ * NTOT];                  // z, fp16, batch-major [b][n]
__device__ float  g_tail[4] = {1.0f, 0.0f, 0.0f, 0.0f};     // bias column chunk (k 1296..1299)
__device__ float  g_zero[4] = {0.0f, 0.0f, 0.0f, 0.0f};     // zero padding chunk

// ---------------------------------------------------------------- PTX helpers
DEVI uint32_t smem_u32(const void* p) {
    uint32_t a;
    asm("{ .reg .u64 t; cvta.to.shared.u64 t, %1; cvt.u32.u64 %0, t; }" : "=r"(a) : "l"(p));
    return a;
}
DEVI void cpa16(uint32_t dst, const void* src) {
    asm volatile("cp.async.cg.shared.global [%0], [%1], 16;" :: "r"(dst), "l"(src) : "memory");
}
DEVI void cp_commit() { asm volatile("cp.async.commit_group;" ::: "memory"); }
DEVI void cp_waitp()  { asm volatile("cp.async.wait_group %0;" :: "n"(NST - 2) : "memory"); }

DEVI void mma_f16(float* d, const uint32_t* a, const uint32_t* b) {
    asm volatile(
        "mma.sync.aligned.m16n8k16.row.col.f32.f16.f16.f32 "
        "{%0,%1,%2,%3}, {%4,%5,%6,%7}, {%8,%9}, {%0,%1,%2,%3};"
        : "+f"(d[0]), "+f"(d[1]), "+f"(d[2]), "+f"(d[3])
        : "r"(a[0]), "r"(a[1]), "r"(a[2]), "r"(a[3]), "r"(b[0]), "r"(b[1]));
}
DEVI uint32_t pack_h2(float a, float b) {   // 2 fp32 -> packed fp16x2 (RN)
    __half2 h = __floats2half2_rn(a, b);
    return *(const uint32_t*)&h;
}

// ------------------- kernel 1: G pack (gather form, coalesced half2 writes)
// G blocks (heavy-first): 0=i 1=f 2=o 3=cand 4=tx 5=tt
// k layout: [0,256)=x [256,768)=h [768,1280)=c [1280,1296)=delt 1296=bias rest 0
// physical: per (g=n/128, kt) block of 4096 halves, element
//   d = ((ks*512 + c*4 + tig)<<2) + jj  holds G[g*128+c][kt*32 + ks*16 +
//   {2tig, 2tig+1, 2tig+8, 2tig+9}[jj]]
DEVI float fetchG(
    int blk, int j, int k,
    const float* Wix, const float* bix, const float* Wih, const float* Wic,
    const float* Wfx, const float* bfx, const float* Wfh, const float* Wfc,
    const float* Wtx, const float* btx, const float* Wtt,
    const float* Wcx, const float* bcx, const float* Wch,
    const float* Wox, const float* bxo, const float* Woh, const float* Woc,
    const float* Wot) {
    float v = 0.0f;
    if (blk == 0) {        // i
        if      (k < 256)   v = Wix[j * 256 + k];
        else if (k < 768)   v = Wih[j * 512 + k - 256];
        else if (k < 1280)  v = Wic[j * 512 + k - 768];
        else if (k == 1296) v = bix[j];
    } else if (blk == 1) { // f
        if      (k < 256)   v = Wfx[j * 256 + k];
        else if (k < 768)   v = Wfh[j * 512 + k - 256];
        else if (k < 1280)  v = Wfc[j * 512 + k - 768];
        else if (k == 1296) v = bfx[j];
    } else if (blk == 2) { // o
        if      (k < 256)   v = Wox[j * 256 + k];
        else if (k < 768)   v = Woh[j * 512 + k - 256];
        else if (k < 1280)  v = Woc[j * 512 + k - 768];
        else if (k < 1296)  v = Wot[j * 16 + k - 1280];
        else if (k == 1296) v = bxo[j];
    } else if (blk == 3) { // cand
        if      (k < 256)   v = Wcx[j * 256 + k];
        else if (k < 768)   v = Wch[j * 512 + k - 256];
        else if (k == 1296) v = bcx[j];
    } else if (blk == 4) { // tx
        if      (k < 256)   v = Wtx[j * 256 + k];
        else if (k == 1296) v = btx[j];
    } else {               // tt
        if (k >= 1280 && k < 1296) v = Wtt[j * 16 + k - 1280];
    }
    return v;
}

__global__ void __launch_bounds__(256) pack_G(
    const float* __restrict__ Wix, const float* __restrict__ bix,
    const float* __restrict__ Wih, const float* __restrict__ Wic,
    const float* __restrict__ Wfx, const float* __restrict__ bfx,
    const float* __restrict__ Wfh, const float* __restrict__ Wfc,
    const float* __restrict__ Wtx, const float* __restrict__ btx,
    const float* __restrict__ Wtt,
    const float* __restrict__ Wcx, const float* __restrict__ bcx,
    const float* __restrict__ Wch,
    const float* __restrict__ Wox, const float* __restrict__ bxo,
    const float* __restrict__ Woh, const float* __restrict__ Woc,
    const float* __restrict__ Wot) {
    const int bk = blockIdx.y;            // g*NKT + kt, 24*41 = 984
    const int g  = bk / NKT;
    const int kt = bk - g * NKT;
    const int d  = (blockIdx.x * 256 + threadIdx.x) * 2;   // grid.x = 8 -> d in [0,4096)
    const int jjp = (d >> 1) & 1;         // 0: k pair {0,1}; 1: {8,9} offset
    const int tig = (d >> 2) & 3;
    const int c   = (d >> 4) & 127;
    const int ks  = d >> 11;
    const int n   = g * 128 + c;
    const int blk = n >> 9, j = n & 511;
    const int k   = kt * 32 + ks * 16 + 2 * tig + (jjp ? 8 : 0);
    float v0 = fetchG(blk, j, k,     Wix, bix, Wih, Wic, Wfx, bfx, Wfh, Wfc,
                      Wtx, btx, Wtt, Wcx, bcx, Wch, Wox, bxo, Woh, Woc, Wot);
    float v1 = fetchG(blk, j, k + 1, Wix, bix, Wih, Wic, Wfx, bfx, Wfh, Wfc,
                      Wtx, btx, Wtt, Wcx, bcx, Wch, Wox, bxo, Woh, Woc, Wot);
    __half2 hv = __floats2half2_rn(v0, v1);
    *(__half2*)(g_Gp + (size_t)bk * 4096 + d) = hv;
}

// --------------------------------------------- kernel 2: mma.sync fp16 GEMM
// z[b][n] = sum_k U[b][k]*G[n][k]; A streamed fp32 straight from x/h/c/delt,
// converted to fp16 in-register at fragment load time (== __float2half_rn).
__global__ void __launch_bounds__(256, 1) gemm_k(
    const float* __restrict__ xin, const float* __restrict__ hin,
    const float* __restrict__ cin, const float* __restrict__ dlin) {
    extern __shared__ char smraw[];
    const uint32_t sm0 = smem_u32(smraw);
    const int tid = threadIdx.x, wid = tid >> 5, lane = tid & 31;
    const int gid = lane >> 2, tig = lane & 3;
    const int m0 = blockIdx.x * BM, n0 = blockIdx.y * BN;

    // heavy-first block order: i,f,o,cand,tx,tt
    const int limtab[6] = {40, 40, 40, 24, 8, 0};
    const int lim  = limtab[n0 >> 9];
    const int numk = lim + 1;

    // warp tile 64x64: warps arranged 4(m) x 2(n)
    const int wm = (wid >> 1) * 64;
    const int wn = (wid & 1) * 64;

    float acc[4][8][4];
    #pragma unroll
    for (int mi = 0; mi < 4; mi++)
        #pragma unroll
        for (int ni = 0; ni < 8; ni++)
            #pragma unroll
            for (int r = 0; r < 4; r++) acc[mi][ni][r] = 0.0f;

    // cooperative tile load: pipeline slot t -> k-tile kt
    auto load_tile = [&](int t) {
        const int s  = t % NST;
        const int kt = (t < lim) ? t : (NKT - 1);
        const uint32_t ab = sm0 + s * STG;
        const uint32_t bb = ab + ASTG;
        // A: fp32, 2048 chunks of 16B straight from source tensors
        #pragma unroll
        for (int i = 0; i < 8; i++) {
            int ch = tid + i * 256, r = ch >> 3, c = ch & 7;
            int b = m0 + r;
            const char* src;
            if (kt < 8)
                src = (const char*)(xin + (size_t)b * 256 + kt * 32) + c * 16;
            else if (kt < 24)
                src = (const char*)(hin + (size_t)b * 512 + kt * 32 - 256) + c * 16;
            else if (kt < 40)
                src = (const char*)(cin + (size_t)b * 512 + kt * 32 - 768) + c * 16;
            else {
                if (c < 4)       src = (const char*)(dlin + (size_t)b * 16) + c * 16;
                else if (c == 4) src = (const char*)g_tail;
                else             src = (const char*)g_zero;
            }
            cpa16(ab + (uint32_t)(r * (APADF * 4) + c * 16), src);
        }
        // B: fp16 permuted, 512 chunks of 16B contiguous
        const char* Bsrc = (const char*)(g_Gp + (size_t)((n0 >> 7) * NKT + kt) * 4096);
        #pragma unroll
        for (int i = 0; i < 2; i++) {
            int ch = tid + i * 256;
            cpa16(bb + (uint32_t)(ch * 16), Bsrc + (size_t)ch * 16);
        }
        cp_commit();
    };

    // prologue: NST-1 committed groups (real or empty)
    #pragma unroll
    for (int p = 0; p < NST - 1; p++) {
        if (p < numk) load_tile(p);
        else cp_commit();
    }

    for (int t = 0; t < numk; t++) {
        cp_waitp();             // tile t's group complete (own thread)
        __syncthreads();        // tile t visible to all; all done with tile t-1
        if (t + NST - 1 < numk) load_tile(t + NST - 1);   // refills stage (t-1)%NST
        else cp_commit();

        const int s = t % NST;
        const float* As  = (const float*)(smraw + s * STG);
        const uint2* Bs2 = (const uint2*)(smraw + s * STG + ASTG);

        #pragma unroll
        for (int ks = 0; ks < 2; ks++) {
            const int k0 = ks * 16;
            uint32_t af[4][4], bf[8][2];
            #pragma unroll
            for (int mi = 0; mi < 4; mi++) {
                int r0 = wm + mi * 16 + gid;
                float2 v0 = *(const float2*)(As + r0 * APADF + k0 + 2 * tig);
                float2 v1 = *(const float2*)(As + (r0 + 8) * APADF + k0 + 2 * tig);
                float2 v2 = *(const float2*)(As + r0 * APADF + k0 + 2 * tig + 8);
                float2 v3 = *(const float2*)(As + (r0 + 8) * APADF + k0 + 2 * tig + 8);
                af[mi][0] = pack_h2(v0.x, v0.y);
                af[mi][1] = pack_h2(v1.x, v1.y);
                af[mi][2] = pack_h2(v2.x, v2.y);
                af[mi][3] = pack_h2(v3.x, v3.y);
            }
            #pragma unroll
            for (int ni = 0; ni < 8; ni++) {
                uint2 v = Bs2[ks * 512 + (wn + ni * 8 + gid) * 4 + tig];
                bf[ni][0] = v.x;
                bf[ni][1] = v.y;
            }
            #pragma unroll
            for (int mi = 0; mi < 4; mi++)
                #pragma unroll
                for (int ni = 0; ni < 8; ni++)
                    mma_f16(acc[mi][ni], af[mi], bf[ni]);
        }
    }

    // epilogue: z[b][n] as fp16 half2 (column pairs)
    #pragma unroll
    for (int mi = 0; mi < 4; mi++) {
        int row0 = m0 + wm + mi * 16 + gid;
        #pragma unroll
        for (int ni = 0; ni < 8; ni++) {
            int col = n0 + wn + ni * 8 + tig * 2;
            __half2 lo = __floats2half2_rn(acc[mi][ni][0], acc[mi][ni][1]);
            __half2 hi = __floats2half2_rn(acc[mi][ni][2], acc[mi][ni][3]);
            *(__half2*)(g_zh + (size_t)row0 * NTOT + col) = lo;
            *(__half2*)(g_zh + (size_t)(row0 + 8) * NTOT + col) = hi;
        }
    }
}

// --------------------------------- kernel 3: gates (z[b][n] -> h, c, T)
DEVI float sigf(float v) { return 1.0f / (1.0f + __expf(-v)); }
DEVI float4 ld_z4(const __half* p) {   // 4 consecutive fp16 -> float4
    uint2 u = *(const uint2*)p;
    float2 a = __half22float2(*(const __half2*)&u.x);
    float2 b = __half22float2(*(const __half2*)&u.y);
    return make_float4(a.x, a.y, b.x, b.y);
}

__global__ void __launch_bounds__(256) elem_k(const float* __restrict__ cprev,
                                              float* __restrict__ out) {
    int idx = blockIdx.x * 256 + threadIdx.x;       // one float4 of H per thread
    if (idx >= B_ * (H_ / 4)) return;
    int b = idx >> 7, j = (idx & 127) * 4;
    const __half* zb = g_zh + (size_t)b * NTOT + j;
    // block order: i=0 f=512 o=1024 cand=1536 tx=2048 tt=2560
    float4 zi = ld_z4(zb);
    float4 zf = ld_z4(zb + 512);
    float4 zo = ld_z4(zb + 1024);
    float4 zk = ld_z4(zb + 1536);
    float4 zt = ld_z4(zb + 2048);
    float4 zd = ld_z4(zb + 2560);
    float4 cp = *(const float4*)(cprev + (size_t)b * H_ + j);

    float zi_[4] = {zi.x, zi.y, zi.z, zi.w};
    float zf_[4] = {zf.x, zf.y, zf.z, zf.w};
    float zo_[4] = {zo.x, zo.y, zo.z, zo.w};
    float zk_[4] = {zk.x, zk.y, zk.z, zk.w};
    float zt_[4] = {zt.x, zt.y, zt.z, zt.w};
    float zd_[4] = {zd.x, zd.y, zd.z, zd.w};
    float cp_[4] = {cp.x, cp.y, cp.z, cp.w};
    float hn[4], cn[4], Tg[4];
    #pragma unroll
    for (int r = 0; r < 4; r++) {
        float i_ = sigf(zi_[r]);
        float f_ = sigf(zf_[r]);
        float T_ = sigf(zt_[r] + sigf(zd_[r]));
        float k_ = tanhf(zk_[r]);
        float o_ = sigf(zo_[r]);
        float c_ = i_ * T_ * k_ + f_ * cp_[r];
        hn[r] = o_ * tanhf(c_);
        cn[r] = c_;
        Tg[r] = T_;
    }
    size_t off = (size_t)b * H_ + j;
    *(float4*)(out + off)                      = make_float4(hn[0], hn[1], hn[2], hn[3]);
    *(float4*)(out + (size_t)B_ * H_ + off)    = make_float4(cn[0], cn[1], cn[2], cn[3]);
    *(float4*)(out + (size_t)2 * B_ * H_ + off)= make_float4(Tg[0], Tg[1], Tg[2], Tg[3]);
}

// ---------------------------------------------------------------- launcher
extern "C" void kernel_launch(void* const* d_in, const int* in_sizes, int n_in,
                              void* d_out, int out_size) {
    const float* x    = (const float*)d_in[0];
    const float* h    = (const float*)d_in[1];
    const float* cprev= (const float*)d_in[2];
    const float* delt = (const float*)d_in[3];
    const float* Wix = (const float*)d_in[4];  const float* bix = (const float*)d_in[5];
    const float* Wih = (const float*)d_in[6];  const float* Wic = (const float*)d_in[7];
    const float* Wfx = (const float*)d_in[8];  const float* bfx = (const float*)d_in[9];
    const float* Wfh = (const float*)d_in[10]; const float* Wfc = (const float*)d_in[11];
    const float* Wtx = (const float*)d_in[12]; const float* btx = (const float*)d_in[13];
    const float* Wtt = (const float*)d_in[14];
    const float* Wcx = (const float*)d_in[15]; const float* bcx = (const float*)d_in[16];
    const float* Wch = (const float*)d_in[17];
    const float* Wox = (const float*)d_in[18]; const float* bxo = (const float*)d_in[19];
    const float* Woh = (const float*)d_in[20]; const float* Woc = (const float*)d_in[21];
    const float* Wot = (const float*)d_in[22];

    cudaFuncSetAttribute(gemm_k, cudaFuncAttributeMaxDynamicSharedMemorySize, SMEM_GEMM);

    {
        dim3 grid(8, (NTOT / 128) * NKT);   // 8 x 984
        pack_G<<<grid, 256>>>(Wix, bix, Wih, Wic, Wfx, bfx, Wfh, Wfc,
                              Wtx, btx, Wtt, Wcx, bcx, Wch,
                              Wox, bxo, Woh, Woc, Wot);
    }
    {
        dim3 grid(B_ / BM, NTOT / BN);   // 64 x 24, heavy blocks first in y
        gemm_k<<<grid, 256, SMEM_GEMM>>>(x, h, cprev, delt);
    }
    {
        int tot = B_ * (H_ / 4);
        elem_k<<<(tot + 255) / 256, 256>>>(cprev, (float*)d_out);
    }
}

// round 16
// speedup vs baseline: 1.3344x; 1.3344x over previous
#include <cuda_runtime.h>
#include <cuda_fp16.h>
#include <cstdint>
#include <cstddef>

#define DEVI __device__ __forceinline__

static constexpr int B_   = 16384;
static constexpr int H_   = 512;
static constexpr int KP   = 1312;   // padded K: 41 tiles of 32
static constexpr int NKT  = 41;
static constexpr int NTOT = 3072;   // 6 gate blocks * 512

// GEMM tiling
static constexpr int BM = 256, BN = 128, BK = 32;
static constexpr int NST = 6;                        // cp.async stages
static constexpr int APADH = 40;                     // A row stride in halves (80 B)
static constexpr int ASTG = BM * APADH * 2;          // 20480 B
static constexpr int BSTG = BN * BK * 2;             // 8192 B (fragment-packed)
static constexpr int STG  = ASTG + BSTG;             // 28672 B
static constexpr int SMEM_GEMM = NST * STG;          // 172032 B

// n-block order (heavy-first): 0=i 1=f 2=o 3=cand 4=tx 5=tt
__device__ __half g_Uh[(size_t)B_ * KP];                    // fp16 packed activations
__device__ __half g_Gp[(size_t)(NTOT / 128) * NKT * 4096];  // permuted fp16 weights
__device__ __half g_zh[(size_t)B_ * NTOT];                  // z, fp16, batch-major [b][n]

// ---------------------------------------------------------------- PTX helpers
DEVI uint32_t smem_u32(const void* p) {
    uint32_t a;
    asm("{ .reg .u64 t; cvta.to.shared.u64 t, %1; cvt.u32.u64 %0, t; }" : "=r"(a) : "l"(p));
    return a;
}
DEVI void cpa16(uint32_t dst, const void* src) {
    asm volatile("cp.async.cg.shared.global [%0], [%1], 16;" :: "r"(dst), "l"(src) : "memory");
}
DEVI void cp_commit() { asm volatile("cp.async.commit_group;" ::: "memory"); }
DEVI void cp_waitp()  { asm volatile("cp.async.wait_group %0;" :: "n"(NST - 2) : "memory"); }

DEVI void mma_f16(float* d, const uint32_t* a, const uint32_t* b) {
    asm volatile(
        "mma.sync.aligned.m16n8k16.row.col.f32.f16.f16.f32 "
        "{%0,%1,%2,%3}, {%4,%5,%6,%7}, {%8,%9}, {%0,%1,%2,%3};"
        : "+f"(d[0]), "+f"(d[1]), "+f"(d[2]), "+f"(d[3])
        : "r"(a[0]), "r"(a[1]), "r"(a[2]), "r"(a[3]), "r"(b[0]), "r"(b[1]));
}

// ------------------- weight gather (per logical G[n][k], heavy-first blocks)
DEVI float fetchG(
    int blk, int j, int k,
    const float* Wix, const float* bix, const float* Wih, const float* Wic,
    const float* Wfx, const float* bfx, const float* Wfh, const float* Wfc,
    const float* Wtx, const float* btx, const float* Wtt,
    const float* Wcx, const float* bcx, const float* Wch,
    const float* Wox, const float* bxo, const float* Woh, const float* Woc,
    const float* Wot) {
    float v = 0.0f;
    if (blk == 0) {        // i
        if      (k < 256)   v = Wix[j * 256 + k];
        else if (k < 768)   v = Wih[j * 512 + k - 256];
        else if (k < 1280)  v = Wic[j * 512 + k - 768];
        else if (k == 1296) v = bix[j];
    } else if (blk == 1) { // f
        if      (k < 256)   v = Wfx[j * 256 + k];
        else if (k < 768)   v = Wfh[j * 512 + k - 256];
        else if (k < 1280)  v = Wfc[j * 512 + k - 768];
        else if (k == 1296) v = bfx[j];
    } else if (blk == 2) { // o
        if      (k < 256)   v = Wox[j * 256 + k];
        else if (k < 768)   v = Woh[j * 512 + k - 256];
        else if (k < 1280)  v = Woc[j * 512 + k - 768];
        else if (k < 1296)  v = Wot[j * 16 + k - 1280];
        else if (k == 1296) v = bxo[j];
    } else if (blk == 3) { // cand
        if      (k < 256)   v = Wcx[j * 256 + k];
        else if (k < 768)   v = Wch[j * 512 + k - 256];
        else if (k == 1296) v = bcx[j];
    } else if (blk == 4) { // tx
        if      (k < 256)   v = Wtx[j * 256 + k];
        else if (k == 1296) v = btx[j];
    } else {               // tt
        if (k >= 1280 && k < 1296) v = Wtt[j * 16 + k - 1280];
    }
    return v;
}

// ------------- kernel 1: merged prep (whole-block routing, no thread div.)
// blocks [0, B_): U pack row b   |   blocks [B_, B_+7872): G pack chunk
// U[b][k]: [0,256)=x [256,768)=h [768,1280)=c [1280,1296)=delt 1296=1 rest 0
// G physical: per (g=n/128, kt) block of 4096 halves, element
//   d = ((ks*512 + c*4 + tig)<<2) + jj  holds G[g*128+c][kt*32 + ks*16 +
//   {2tig, 2tig+1, 2tig+8, 2tig+9}[jj]]
__global__ void __launch_bounds__(256) prep_k(
    const float* __restrict__ x, const float* __restrict__ h,
    const float* __restrict__ cp, const float* __restrict__ dl,
    const float* __restrict__ Wix, const float* __restrict__ bix,
    const float* __restrict__ Wih, const float* __restrict__ Wic,
    const float* __restrict__ Wfx, const float* __restrict__ bfx,
    const float* __restrict__ Wfh, const float* __restrict__ Wfc,
    const float* __restrict__ Wtx, const float* __restrict__ btx,
    const float* __restrict__ Wtt,
    const float* __restrict__ Wcx, const float* __restrict__ bcx,
    const float* __restrict__ Wch,
    const float* __restrict__ Wox, const float* __restrict__ bxo,
    const float* __restrict__ Woh, const float* __restrict__ Woc,
    const float* __restrict__ Wot) {
    if (blockIdx.x < (unsigned)B_) {
        // ---- U pack: one row, float4 chunks, division-free ----
        const int b = blockIdx.x;
        __half* dst = g_Uh + (size_t)b * KP;
        for (int k4 = threadIdx.x; k4 < KP / 4; k4 += 256) {
            float4 v;
            if      (k4 < 64)  v = *(const float4*)(x  + (size_t)b * 256 + k4 * 4);
            else if (k4 < 192) v = *(const float4*)(h  + (size_t)b * 512 + (k4 - 64) * 4);
            else if (k4 < 320) v = *(const float4*)(cp + (size_t)b * 512 + (k4 - 192) * 4);
            else if (k4 < 324) v = *(const float4*)(dl + (size_t)b * 16  + (k4 - 320) * 4);
            else if (k4 == 324) v = make_float4(1.0f, 0.0f, 0.0f, 0.0f);
            else                v = make_float4(0.0f, 0.0f, 0.0f, 0.0f);
            __half2 lo = __floats2half2_rn(v.x, v.y);
            __half2 hi = __floats2half2_rn(v.z, v.w);
            uint2 u;
            u.x = *(const uint32_t*)&lo;
            u.y = *(const uint32_t*)&hi;
            *(uint2*)(dst + k4 * 4) = u;
        }
        return;
    }
    // ---- G pack: gather form, coalesced half2 writes ----
    const int p  = blockIdx.x - B_;        // 0..7871
    const int bk = p >> 3;                 // g*NKT + kt  (984)
    const int xc = p & 7;                  // chunk within block
    const int g  = bk / NKT;
    const int kt = bk - g * NKT;
    const int d  = (xc * 256 + threadIdx.x) * 2;   // d in [0,4096)
    const int jjp = (d >> 1) & 1;
    const int tig = (d >> 2) & 3;
    const int c   = (d >> 4) & 127;
    const int ks  = d >> 11;
    const int n   = g * 128 + c;
    const int blk = n >> 9, j = n & 511;
    const int k   = kt * 32 + ks * 16 + 2 * tig + (jjp ? 8 : 0);
    float v0 = fetchG(blk, j, k,     Wix, bix, Wih, Wic, Wfx, bfx, Wfh, Wfc,
                      Wtx, btx, Wtt, Wcx, bcx, Wch, Wox, bxo, Woh, Woc, Wot);
    float v1 = fetchG(blk, j, k + 1, Wix, bix, Wih, Wic, Wfx, bfx, Wfh, Wfc,
                      Wtx, btx, Wtt, Wcx, bcx, Wch, Wox, bxo, Woh, Woc, Wot);
    __half2 hv = __floats2half2_rn(v0, v1);
    *(__half2*)(g_Gp + (size_t)bk * 4096 + d) = hv;
}

// --------------------------------------------- kernel 2: mma.sync fp16 GEMM
// z[b][n] = sum_k U[b][k]*G[n][k];  CTA tile 256(batch) x 128(gate cols)
__global__ void __launch_bounds__(256, 1) gemm_k() {
    extern __shared__ char smraw[];
    const uint32_t sm0 = smem_u32(smraw);
    const int tid = threadIdx.x, wid = tid >> 5, lane = tid & 31;
    const int gid = lane >> 2, tig = lane & 3;
    const int m0 = blockIdx.x * BM, n0 = blockIdx.y * BN;

    // heavy-first block order: i,f,o,cand,tx,tt
    const int limtab[6] = {40, 40, 40, 24, 8, 0};
    const int lim  = limtab[n0 >> 9];
    const int numk = lim + 1;

    // warp tile 64x64: warps arranged 4(m) x 2(n)
    const int wm = (wid >> 1) * 64;
    const int wn = (wid & 1) * 64;

    float acc[4][8][4];
    #pragma unroll
    for (int mi = 0; mi < 4; mi++)
        #pragma unroll
        for (int ni = 0; ni < 8; ni++)
            #pragma unroll
            for (int r = 0; r < 4; r++) acc[mi][ni][r] = 0.0f;

    // cooperative tile load: pipeline slot t -> k-tile kt
    auto load_tile = [&](int t) {
        const int s  = t % NST;
        const int kt = (t < lim) ? t : (NKT - 1);
        const uint32_t ab = sm0 + s * STG;
        const uint32_t bb = ab + ASTG;
        // A: 1024 chunks of 16B from g_Uh (row = 64 B of fp16)
        #pragma unroll
        for (int i = 0; i < 4; i++) {
            int ch = tid + i * 256, r = ch >> 2, c = ch & 3;
            cpa16(ab + (uint32_t)(r * (APADH * 2) + c * 16),
                  (const char*)(g_Uh + (size_t)(m0 + r) * KP + kt * 32) + c * 16);
        }
        // B: 512 chunks of 16B, contiguous copy of permuted block
        const char* Bsrc = (const char*)(g_Gp + (size_t)((n0 >> 7) * NKT + kt) * 4096);
        #pragma unroll
        for (int i = 0; i < 2; i++) {
            int ch = tid + i * 256;
            cpa16(bb + (uint32_t)(ch * 16), Bsrc + (size_t)ch * 16);
        }
        cp_commit();
    };

    // prologue: NST-1 committed groups (real or empty)
    #pragma unroll
    for (int p = 0; p < NST - 1; p++) {
        if (p < numk) load_tile(p);
        else cp_commit();
    }

    for (int t = 0; t < numk; t++) {
        cp_waitp();             // tile t's group complete (own thread)
        __syncthreads();        // tile t visible to all; all done with tile t-1
        if (t + NST - 1 < numk) load_tile(t + NST - 1);   // refills stage (t-1)%NST
        else cp_commit();

        const int s = t % NST;
        const __half* As  = (const __half*)(smraw + s * STG);
        const uint2*  Bs2 = (const uint2*)(smraw + s * STG + ASTG);

        #pragma unroll
        for (int ks = 0; ks < 2; ks++) {
            const int k0 = ks * 16;
            uint32_t af[4][4], bf[8][2];
            #pragma unroll
            for (int mi = 0; mi < 4; mi++) {
                int r0 = wm + mi * 16 + gid;
                af[mi][0] = *(const uint32_t*)(As + r0 * APADH + k0 + 2 * tig);
                af[mi][1] = *(const uint32_t*)(As + (r0 + 8) * APADH + k0 + 2 * tig);
                af[mi][2] = *(const uint32_t*)(As + r0 * APADH + k0 + 2 * tig + 8);
                af[mi][3] = *(const uint32_t*)(As + (r0 + 8) * APADH + k0 + 2 * tig + 8);
            }
            #pragma unroll
            for (int ni = 0; ni < 8; ni++) {
                uint2 v = Bs2[ks * 512 + (wn + ni * 8 + gid) * 4 + tig];
                bf[ni][0] = v.x;
                bf[ni][1] = v.y;
            }
            #pragma unroll
            for (int mi = 0; mi < 4; mi++)
                #pragma unroll
                for (int ni = 0; ni < 8; ni++)
                    mma_f16(acc[mi][ni], af[mi], bf[ni]);
        }
    }

    // epilogue: z[b][n] as fp16 half2 (column pairs)
    #pragma unroll
    for (int mi = 0; mi < 4; mi++) {
        int row0 = m0 + wm + mi * 16 + gid;
        #pragma unroll
        for (int ni = 0; ni < 8; ni++) {
            int col = n0 + wn + ni * 8 + tig * 2;
            __half2 lo = __floats2half2_rn(acc[mi][ni][0], acc[mi][ni][1]);
            __half2 hi = __floats2half2_rn(acc[mi][ni][2], acc[mi][ni][3]);
            *(__half2*)(g_zh + (size_t)row0 * NTOT + col) = lo;
            *(__half2*)(g_zh + (size_t)(row0 + 8) * NTOT + col) = hi;
        }
    }
}

// --------------------------------- kernel 3: gates (z[b][n] -> h, c, T)
DEVI float sigf(float v) {            // fast sigmoid: ~2^-21 rel err
    return __fdividef(1.0f, 1.0f + __expf(-v));
}
DEVI float tanh_fast(float v) {       // tanh via exp: ~1e-6 abs err
    return 1.0f - __fdividef(2.0f, __expf(2.0f * v) + 1.0f);
}
DEVI float4 ld_z4(const __half* p) {   // 4 consecutive fp16 -> float4
    uint2 u = *(const uint2*)p;
    float2 a = __half22float2(*(const __half2*)&u.x);
    float2 b = __half22float2(*(const __half2*)&u.y);
    return make_float4(a.x, a.y, b.x, b.y);
}

__global__ void __launch_bounds__(256) elem_k(const float* __restrict__ cprev,
                                              float* __restrict__ out) {
    int idx = blockIdx.x * 256 + threadIdx.x;       // one float4 of H per thread
    if (idx >= B_ * (H_ / 4)) return;
    int b = idx >> 7, j = (idx & 127) * 4;
    const __half* zb = g_zh + (size_t)b * NTOT + j;
    // block order: i=0 f=512 o=1024 cand=1536 tx=2048 tt=2560
    float4 zi = ld_z4(zb);
    float4 zf = ld_z4(zb + 512);
    float4 zo = ld_z4(zb + 1024);
    float4 zk = ld_z4(zb + 1536);
    float4 zt = ld_z4(zb + 2048);
    float4 zd = ld_z4(zb + 2560);
    float4 cp = *(const float4*)(cprev + (size_t)b * H_ + j);

    float zi_[4] = {zi.x, zi.y, zi.z, zi.w};
    float zf_[4] = {zf.x, zf.y, zf.z, zf.w};
    float zo_[4] = {zo.x, zo.y, zo.z, zo.w};
    float zk_[4] = {zk.x, zk.y, zk.z, zk.w};
    float zt_[4] = {zt.x, zt.y, zt.z, zt.w};
    float zd_[4] = {zd.x, zd.y, zd.z, zd.w};
    float cp_[4] = {cp.x, cp.y, cp.z, cp.w};
    float hn[4], cn[4], Tg[4];
    #pragma unroll
    for (int r = 0; r < 4; r++) {
        float i_ = sigf(zi_[r]);
        float f_ = sigf(zf_[r]);
        float T_ = sigf(zt_[r] + sigf(zd_[r]));
        float k_ = tanh_fast(zk_[r]);
        float o_ = sigf(zo_[r]);
        float c_ = i_ * T_ * k_ + f_ * cp_[r];
        hn[r] = o_ * tanh_fast(c_);
        cn[r] = c_;
        Tg[r] = T_;
    }
    size_t off = (size_t)b * H_ + j;
    *(float4*)(out + off)                      = make_float4(hn[0], hn[1], hn[2], hn[3]);
    *(float4*)(out + (size_t)B_ * H_ + off)    = make_float4(cn[0], cn[1], cn[2], cn[3]);
    *(float4*)(out + (size_t)2 * B_ * H_ + off)= make_float4(Tg[0], Tg[1], Tg[2], Tg[3]);
}

// ---------------------------------------------------------------- launcher
extern "C" void kernel_launch(void* const* d_in, const int* in_sizes, int n_in,
                              void* d_out, int out_size) {
    const float* x    = (const float*)d_in[0];
    const float* h    = (const float*)d_in[1];
    const float* cprev= (const float*)d_in[2];
    const float* delt = (const float*)d_in[3];
    const float* Wix = (const float*)d_in[4];  const float* bix = (const float*)d_in[5];
    const float* Wih = (const float*)d_in[6];  const float* Wic = (const float*)d_in[7];
    const float* Wfx = (const float*)d_in[8];  const float* bfx = (const float*)d_in[9];
    const float* Wfh = (const float*)d_in[10]; const float* Wfc = (const float*)d_in[11];
    const float* Wtx = (const float*)d_in[12]; const float* btx = (const float*)d_in[13];
    const float* Wtt = (const float*)d_in[14];
    const float* Wcx = (const float*)d_in[15]; const float* bcx = (const float*)d_in[16];
    const float* Wch = (const float*)d_in[17];
    const float* Wox = (const float*)d_in[18]; const float* bxo = (const float*)d_in[19];
    const float* Woh = (const float*)d_in[20]; const float* Woc = (const float*)d_in[21];
    const float* Wot = (const float*)d_in[22];

    cudaFuncSetAttribute(gemm_k, cudaFuncAttributeMaxDynamicSharedMemorySize, SMEM_GEMM);

    {
        // merged prep: 16384 U blocks + 7872 G blocks
        unsigned nb = (unsigned)(B_ + (NTOT / 128) * NKT * 8);
        prep_k<<<nb, 256>>>(x, h, cprev, delt,
                            Wix, bix, Wih, Wic, Wfx, bfx, Wfh, Wfc,
                            Wtx, btx, Wtt, Wcx, bcx, Wch,
                            Wox, bxo, Woh, Woc, Wot);
    }
    {
        dim3 grid(B_ / BM, NTOT / BN);   // 64 x 24, heavy blocks first in y
        gemm_k<<<grid, 256, SMEM_GEMM>>>();
    }
    {
        int tot = B_ * (H_ / 4);
        elem_k<<<(tot + 255) / 256, 256>>>(cprev, (float*)d_out);
    }
}

// round 17
// speedup vs baseline: 1.3415x; 1.0053x over previous
#include <cuda_runtime.h>
#include <cuda_fp16.h>
#include <cstdint>
#include <cstddef>

#define DEVI __device__ __forceinline__

static constexpr int B_   = 16384;
static constexpr int H_   = 512;
static constexpr int KP   = 1312;   // padded K: 41 tiles of 32
static constexpr int NKT  = 41;
static constexpr int NTOT = 3072;   // 6 gate blocks * 512

// GEMM tiling
static constexpr int BM = 256, BN = 128, BK = 32;
static constexpr int NST = 6;                        // cp.async stages
static constexpr int APADH = 40;                     // A row stride in halves (80 B)
static constexpr int ASTG = BM * APADH * 2;          // 20480 B
static constexpr int BSTG = BN * BK * 2;             // 8192 B (fragment-packed)
static constexpr int STG  = ASTG + BSTG;             // 28672 B
static constexpr int SMEM_GEMM = NST * STG;          // 172032 B

// prep grid shaping
static constexpr int U_BLOCKS = 2048;                // 8 rows per CTA
static constexpr int G_BLOCKS = (NTOT / 128) * NKT;  // 984, one per (g,kt)

// n-block order (heavy-first): 0=i 1=f 2=o 3=cand 4=tx 5=tt
__device__ __half g_Uh[(size_t)B_ * KP];                    // fp16 packed activations
__device__ __half g_Gp[(size_t)G_BLOCKS * 4096];            // permuted fp16 weights
__device__ __half g_zh[(size_t)B_ * NTOT];                  // z, fp16, batch-major [b][n]

// ---------------------------------------------------------------- PTX helpers
DEVI uint32_t smem_u32(const void* p) {
    uint32_t a;
    asm("{ .reg .u64 t; cvta.to.shared.u64 t, %1; cvt.u32.u64 %0, t; }" : "=r"(a) : "l"(p));
    return a;
}
DEVI void cpa16(uint32_t dst, const void* src) {
    asm volatile("cp.async.cg.shared.global [%0], [%1], 16;" :: "r"(dst), "l"(src) : "memory");
}
DEVI void cp_commit() { asm volatile("cp.async.commit_group;" ::: "memory"); }
DEVI void cp_waitp()  { asm volatile("cp.async.wait_group %0;" :: "n"(NST - 2) : "memory"); }

DEVI void mma_f16(float* d, const uint32_t* a, const uint32_t* b) {
    asm volatile(
        "mma.sync.aligned.m16n8k16.row.col.f32.f16.f16.f32 "
        "{%0,%1,%2,%3}, {%4,%5,%6,%7}, {%8,%9}, {%0,%1,%2,%3};"
        : "+f"(d[0]), "+f"(d[1]), "+f"(d[2]), "+f"(d[3])
        : "r"(a[0]), "r"(a[1]), "r"(a[2]), "r"(a[3]), "r"(b[0]), "r"(b[1]));
}

// ------------------- weight gather (per logical G[n][k], heavy-first blocks)
DEVI float fetchG(
    int blk, int j, int k,
    const float* Wix, const float* bix, const float* Wih, const float* Wic,
    const float* Wfx, const float* bfx, const float* Wfh, const float* Wfc,
    const float* Wtx, const float* btx, const float* Wtt,
    const float* Wcx, const float* bcx, const float* Wch,
    const float* Wox, const float* bxo, const float* Woh, const float* Woc,
    const float* Wot) {
    float v = 0.0f;
    if (blk == 0) {        // i
        if      (k < 256)   v = Wix[j * 256 + k];
        else if (k < 768)   v = Wih[j * 512 + k - 256];
        else if (k < 1280)  v = Wic[j * 512 + k - 768];
        else if (k == 1296) v = bix[j];
    } else if (blk == 1) { // f
        if      (k < 256)   v = Wfx[j * 256 + k];
        else if (k < 768)   v = Wfh[j * 512 + k - 256];
        else if (k < 1280)  v = Wfc[j * 512 + k - 768];
        else if (k == 1296) v = bfx[j];
    } else if (blk == 2) { // o
        if      (k < 256)   v = Wox[j * 256 + k];
        else if (k < 768)   v = Woh[j * 512 + k - 256];
        else if (k < 1280)  v = Woc[j * 512 + k - 768];
        else if (k < 1296)  v = Wot[j * 16 + k - 1280];
        else if (k == 1296) v = bxo[j];
    } else if (blk == 3) { // cand
        if      (k < 256)   v = Wcx[j * 256 + k];
        else if (k < 768)   v = Wch[j * 512 + k - 256];
        else if (k == 1296) v = bcx[j];
    } else if (blk == 4) { // tx
        if      (k < 256)   v = Wtx[j * 256 + k];
        else if (k == 1296) v = btx[j];
    } else {               // tt
        if (k >= 1280 && k < 1296) v = Wtt[j * 16 + k - 1280];
    }
    return v;
}

// ------------- kernel 1: merged prep, wave-shaped (3032 CTAs total)
// blocks [0, U_BLOCKS): U pack, 8 rows each
// blocks [U_BLOCKS, U_BLOCKS+G_BLOCKS): G pack, one (g,kt) block each
__global__ void __launch_bounds__(256) prep_k(
    const float* __restrict__ x, const float* __restrict__ h,
    const float* __restrict__ cp, const float* __restrict__ dl,
    const float* __restrict__ Wix, const float* __restrict__ bix,
    const float* __restrict__ Wih, const float* __restrict__ Wic,
    const float* __restrict__ Wfx, const float* __restrict__ bfx,
    const float* __restrict__ Wfh, const float* __restrict__ Wfc,
    const float* __restrict__ Wtx, const float* __restrict__ btx,
    const float* __restrict__ Wtt,
    const float* __restrict__ Wcx, const float* __restrict__ bcx,
    const float* __restrict__ Wch,
    const float* __restrict__ Wox, const float* __restrict__ bxo,
    const float* __restrict__ Woh, const float* __restrict__ Woc,
    const float* __restrict__ Wot) {
    if (blockIdx.x < (unsigned)U_BLOCKS) {
        // ---- U pack: 8 rows per CTA, float4 chunks, division-free ----
        #pragma unroll
        for (int rr = 0; rr < 8; rr++) {
            const int b = blockIdx.x * 8 + rr;
            __half* dst = g_Uh + (size_t)b * KP;
            for (int k4 = threadIdx.x; k4 < KP / 4; k4 += 256) {
                float4 v;
                if      (k4 < 64)  v = *(const float4*)(x  + (size_t)b * 256 + k4 * 4);
                else if (k4 < 192) v = *(const float4*)(h  + (size_t)b * 512 + (k4 - 64) * 4);
                else if (k4 < 320) v = *(const float4*)(cp + (size_t)b * 512 + (k4 - 192) * 4);
                else if (k4 < 324) v = *(const float4*)(dl + (size_t)b * 16  + (k4 - 320) * 4);
                else if (k4 == 324) v = make_float4(1.0f, 0.0f, 0.0f, 0.0f);
                else                v = make_float4(0.0f, 0.0f, 0.0f, 0.0f);
                __half2 lo = __floats2half2_rn(v.x, v.y);
                __half2 hi = __floats2half2_rn(v.z, v.w);
                uint2 u;
                u.x = *(const uint32_t*)&lo;
                u.y = *(const uint32_t*)&hi;
                *(uint2*)(dst + k4 * 4) = u;
            }
        }
        return;
    }
    // ---- G pack: one (g,kt) block per CTA; each thread 4 uint2 stores ----
    const int bk = blockIdx.x - U_BLOCKS;  // g*NKT + kt
    const int g  = bk / NKT;
    const int kt = bk - g * NKT;
    #pragma unroll
    for (int i = 0; i < 4; i++) {
        const int q   = i * 256 + threadIdx.x;   // fragment index in [0,1024)
        const int d   = q * 4;                   // first half index
        const int tig = q & 3;
        const int c   = (q >> 2) & 127;
        const int ks  = q >> 9;
        const int n   = g * 128 + c;
        const int blk = n >> 9, j = n & 511;
        const int k0  = kt * 32 + ks * 16 + 2 * tig;
        // 4 fragment halves: k0, k0+1, k0+8, k0+9 (one region, 16-aligned segs)
        float v0 = fetchG(blk, j, k0,     Wix, bix, Wih, Wic, Wfx, bfx, Wfh, Wfc,
                          Wtx, btx, Wtt, Wcx, bcx, Wch, Wox, bxo, Woh, Woc, Wot);
        float v1 = fetchG(blk, j, k0 + 1, Wix, bix, Wih, Wic, Wfx, bfx, Wfh, Wfc,
                          Wtx, btx, Wtt, Wcx, bcx, Wch, Wox, bxo, Woh, Woc, Wot);
        float v2 = fetchG(blk, j, k0 + 8, Wix, bix, Wih, Wic, Wfx, bfx, Wfh, Wfc,
                          Wtx, btx, Wtt, Wcx, bcx, Wch, Wox, bxo, Woh, Woc, Wot);
        float v3 = fetchG(blk, j, k0 + 9, Wix, bix, Wih, Wic, Wfx, bfx, Wfh, Wfc,
                          Wtx, btx, Wtt, Wcx, bcx, Wch, Wox, bxo, Woh, Woc, Wot);
        __half2 lo = __floats2half2_rn(v0, v1);
        __half2 hi = __floats2half2_rn(v2, v3);
        uint2 u;
        u.x = *(const uint32_t*)&lo;
        u.y = *(const uint32_t*)&hi;
        *(uint2*)(g_Gp + (size_t)bk * 4096 + d) = u;
    }
}

// --------------------------------------------- kernel 2: mma.sync fp16 GEMM
// z[b][n] = sum_k U[b][k]*G[n][k];  CTA tile 256(batch) x 128(gate cols)
__global__ void __launch_bounds__(256, 1) gemm_k() {
    extern __shared__ char smraw[];
    const uint32_t sm0 = smem_u32(smraw);
    const int tid = threadIdx.x, wid = tid >> 5, lane = tid & 31;
    const int gid = lane >> 2, tig = lane & 3;
    const int m0 = blockIdx.x * BM, n0 = blockIdx.y * BN;

    // heavy-first block order: i,f,o,cand,tx,tt
    const int limtab[6] = {40, 40, 40, 24, 8, 0};
    const int lim  = limtab[n0 >> 9];
    const int numk = lim + 1;

    // warp tile 64x64: warps arranged 4(m) x 2(n)
    const int wm = (wid >> 1) * 64;
    const int wn = (wid & 1) * 64;

    float acc[4][8][4];
    #pragma unroll
    for (int mi = 0; mi < 4; mi++)
        #pragma unroll
        for (int ni = 0; ni < 8; ni++)
            #pragma unroll
            for (int r = 0; r < 4; r++) acc[mi][ni][r] = 0.0f;

    // cooperative tile load: pipeline slot t -> k-tile kt
    auto load_tile = [&](int t) {
        const int s  = t % NST;
        const int kt = (t < lim) ? t : (NKT - 1);
        const uint32_t ab = sm0 + s * STG;
        const uint32_t bb = ab + ASTG;
        // A: 1024 chunks of 16B from g_Uh (row = 64 B of fp16)
        #pragma unroll
        for (int i = 0; i < 4; i++) {
            int ch = tid + i * 256, r = ch >> 2, c = ch & 3;
            cpa16(ab + (uint32_t)(r * (APADH * 2) + c * 16),
                  (const char*)(g_Uh + (size_t)(m0 + r) * KP + kt * 32) + c * 16);
        }
        // B: 512 chunks of 16B, contiguous copy of permuted block
        const char* Bsrc = (const char*)(g_Gp + (size_t)((n0 >> 7) * NKT + kt) * 4096);
        #pragma unroll
        for (int i = 0; i < 2; i++) {
            int ch = tid + i * 256;
            cpa16(bb + (uint32_t)(ch * 16), Bsrc + (size_t)ch * 16);
        }
        cp_commit();
    };

    // prologue: NST-1 committed groups (real or empty)
    #pragma unroll
    for (int p = 0; p < NST - 1; p++) {
        if (p < numk) load_tile(p);
        else cp_commit();
    }

    for (int t = 0; t < numk; t++) {
        cp_waitp();             // tile t's group complete (own thread)
        __syncthreads();        // tile t visible to all; all done with tile t-1
        if (t + NST - 1 < numk) load_tile(t + NST - 1);   // refills stage (t-1)%NST
        else cp_commit();

        const int s = t % NST;
        const __half* As  = (const __half*)(smraw + s * STG);
        const uint2*  Bs2 = (const uint2*)(smraw + s * STG + ASTG);

        #pragma unroll
        for (int ks = 0; ks < 2; ks++) {
            const int k0 = ks * 16;
            uint32_t af[4][4], bf[8][2];
            #pragma unroll
            for (int mi = 0; mi < 4; mi++) {
                int r0 = wm + mi * 16 + gid;
                af[mi][0] = *(const uint32_t*)(As + r0 * APADH + k0 + 2 * tig);
                af[mi][1] = *(const uint32_t*)(As + (r0 + 8) * APADH + k0 + 2 * tig);
                af[mi][2] = *(const uint32_t*)(As + r0 * APADH + k0 + 2 * tig + 8);
                af[mi][3] = *(const uint32_t*)(As + (r0 + 8) * APADH + k0 + 2 * tig + 8);
            }
            #pragma unroll
            for (int ni = 0; ni < 8; ni++) {
                uint2 v = Bs2[ks * 512 + (wn + ni * 8 + gid) * 4 + tig];
                bf[ni][0] = v.x;
                bf[ni][1] = v.y;
            }
            #pragma unroll
            for (int mi = 0; mi < 4; mi++)
                #pragma unroll
                for (int ni = 0; ni < 8; ni++)
                    mma_f16(acc[mi][ni], af[mi], bf[ni]);
        }
    }

    // epilogue: z[b][n] as fp16 half2 (column pairs)
    #pragma unroll
    for (int mi = 0; mi < 4; mi++) {
        int row0 = m0 + wm + mi * 16 + gid;
        #pragma unroll
        for (int ni = 0; ni < 8; ni++) {
            int col = n0 + wn + ni * 8 + tig * 2;
            __half2 lo = __floats2half2_rn(acc[mi][ni][0], acc[mi][ni][1]);
            __half2 hi = __floats2half2_rn(acc[mi][ni][2], acc[mi][ni][3]);
            *(__half2*)(g_zh + (size_t)row0 * NTOT + col) = lo;
            *(__half2*)(g_zh + (size_t)(row0 + 8) * NTOT + col) = hi;
        }
    }
}

// --------------------------------- kernel 3: gates (z[b][n] -> h, c, T)
DEVI float sigf(float v) {            // fast sigmoid: ~2^-21 rel err
    return __fdividef(1.0f, 1.0f + __expf(-v));
}
DEVI float tanh_fast(float v) {       // tanh via exp: ~1e-6 abs err
    return 1.0f - __fdividef(2.0f, __expf(2.0f * v) + 1.0f);
}
DEVI float4 ld_z4(const __half* p) {   // 4 consecutive fp16 -> float4
    uint2 u = *(const uint2*)p;
    float2 a = __half22float2(*(const __half2*)&u.x);
    float2 b = __half22float2(*(const __half2*)&u.y);
    return make_float4(a.x, a.y, b.x, b.y);
}

__global__ void __launch_bounds__(256) elem_k(const float* __restrict__ cprev,
                                              float* __restrict__ out) {
    int idx = blockIdx.x * 256 + threadIdx.x;       // one float4 of H per thread
    if (idx >= B_ * (H_ / 4)) return;
    int b = idx >> 7, j = (idx & 127) * 4;
    const __half* zb = g_zh + (size_t)b * NTOT + j;
    // block order: i=0 f=512 o=1024 cand=1536 tx=2048 tt=2560
    float4 zi = ld_z4(zb);
    float4 zf = ld_z4(zb + 512);
    float4 zo = ld_z4(zb + 1024);
    float4 zk = ld_z4(zb + 1536);
    float4 zt = ld_z4(zb + 2048);
    float4 zd = ld_z4(zb + 2560);
    float4 cp = *(const float4*)(cprev + (size_t)b * H_ + j);

    float zi_[4] = {zi.x, zi.y, zi.z, zi.w};
    float zf_[4] = {zf.x, zf.y, zf.z, zf.w};
    float zo_[4] = {zo.x, zo.y, zo.z, zo.w};
    float zk_[4] = {zk.x, zk.y, zk.z, zk.w};
    float zt_[4] = {zt.x, zt.y, zt.z, zt.w};
    float zd_[4] = {zd.x, zd.y, zd.z, zd.w};
    float cp_[4] = {cp.x, cp.y, cp.z, cp.w};
    float hn[4], cn[4], Tg[4];
    #pragma unroll
    for (int r = 0; r < 4; r++) {
        float i_ = sigf(zi_[r]);
        float f_ = sigf(zf_[r]);
        float T_ = sigf(zt_[r] + sigf(zd_[r]));
        float k_ = tanh_fast(zk_[r]);
        float o_ = sigf(zo_[r]);
        float c_ = i_ * T_ * k_ + f_ * cp_[r];
        hn[r] = o_ * tanh_fast(c_);
        cn[r] = c_;
        Tg[r] = T_;
    }
    size_t off = (size_t)b * H_ + j;
    *(float4*)(out + off)                      = make_float4(hn[0], hn[1], hn[2], hn[3]);
    *(float4*)(out + (size_t)B_ * H_ + off)    = make_float4(cn[0], cn[1], cn[2], cn[3]);
    *(float4*)(out + (size_t)2 * B_ * H_ + off)= make_float4(Tg[0], Tg[1], Tg[2], Tg[3]);
}

// ---------------------------------------------------------------- launcher
extern "C" void kernel_launch(void* const* d_in, const int* in_sizes, int n_in,
                              void* d_out, int out_size) {
    const float* x    = (const float*)d_in[0];
    const float* h    = (const float*)d_in[1];
    const float* cprev= (const float*)d_in[2];
    const float* delt = (const float*)d_in[3];
    const float* Wix = (const float*)d_in[4];  const float* bix = (const float*)d_in[5];
    const float* Wih = (const float*)d_in[6];  const float* Wic = (const float*)d_in[7];
    const float* Wfx = (const float*)d_in[8];  const float* bfx = (const float*)d_in[9];
    const float* Wfh = (const float*)d_in[10]; const float* Wfc = (const float*)d_in[11];
    const float* Wtx = (const float*)d_in[12]; const float* btx = (const float*)d_in[13];
    const float* Wtt = (const float*)d_in[14];
    const float* Wcx = (const float*)d_in[15]; const float* bcx = (const float*)d_in[16];
    const float* Wch = (const float*)d_in[17];
    const float* Wox = (const float*)d_in[18]; const float* bxo = (const float*)d_in[19];
    const float* Woh = (const float*)d_in[20]; const float* Woc = (const float*)d_in[21];
    const float* Wot = (const float*)d_in[22];

    cudaFuncSetAttribute(gemm_k, cudaFuncAttributeMaxDynamicSharedMemorySize, SMEM_GEMM);

    {
        unsigned nb = (unsigned)(U_BLOCKS + G_BLOCKS);   // 3032 CTAs
        prep_k<<<nb, 256>>>(x, h, cprev, delt,
                            Wix, bix, Wih, Wic, Wfx, bfx, Wfh, Wfc,
                            Wtx, btx, Wtt, Wcx, bcx, Wch,
                            Wox, bxo, Woh, Woc, Wot);
    }
    {
        dim3 grid(B_ / BM, NTOT / BN);   // 64 x 24, heavy blocks first in y
        gemm_k<<<grid, 256, SMEM_GEMM>>>();
    }
    {
        int tot = B_ * (H_ / 4);
        elem_k<<<(tot + 255) / 256, 256>>>(cprev, (float*)d_out);
    }
}